// round 8
// baseline (speedup 1.0000x reference)
#include <cuda_runtime.h>
#include <cstdint>

#define NUM_MESH  40962
#define NUM_GRID  65536
#define EMBED     256
#define NUM_EDGES 262144
#define BATCH     2

// scratch (allocation-free rule: __device__ globals; zero-init at module load)
__device__ int g_deg[NUM_GRID];
__device__ int g_off[NUM_GRID + 1];
__device__ int g_cur[NUM_GRID];
__device__ int g_edges[NUM_EDGES];   // sender index per CSR slot
__device__ int g_blocksum[64];

// edge_index is int32 on device (proven: reading as int64 in R1 produced an
// out-of-bounds access — the buffer is exactly NUM_EDGES*2*4 bytes).

// ---------- degree histogram (g_deg must be zero on entry; see k_scan3) ----------
__global__ void k_deg(const int4* __restrict__ ei) {
    int i = blockIdx.x * blockDim.x + threadIdx.x;   // 2 edges per thread
    if (i < NUM_EDGES / 2) {
        int4 e = __ldg(&ei[i]);        // (s0, r0, s1, r1)
        atomicAdd(&g_deg[e.y], 1);
        atomicAdd(&g_deg[e.w], 1);
    }
}

// ---------- scan pass 1: per-block sums (64 blocks x 256 thr x 4 elems) ----------
__global__ void k_scan1() {
    __shared__ int sh[256];
    int t = threadIdx.x, b = blockIdx.x;
    int4 v = __ldg(&((const int4*)g_deg)[b * 256 + t]);
    sh[t] = v.x + v.y + v.z + v.w;
    __syncthreads();
    for (int st = 128; st > 0; st >>= 1) {
        if (t < st) sh[t] += sh[t + st];
        __syncthreads();
    }
    if (t == 0) g_blocksum[b] = sh[0];
}

// ---------- scan pass 2: local scan + (redundant) scan of 64 block sums ----------
// Also zeroes g_deg after consuming it, so the next call's k_deg starts clean.
__global__ void k_scan3() {
    __shared__ int sh[256];
    int t = threadIdx.x, b = blockIdx.x;
    int base4 = b * 256 + t;                 // int4 index into g_deg
    int4 v = __ldg(&((const int4*)g_deg)[base4]);
    int s = v.x + v.y + v.z + v.w;
    sh[t] = s;
    __syncthreads();
    // Hillis-Steele inclusive scan over 256 thread sums
    for (int st = 1; st < 256; st <<= 1) {
        int add = (t >= st) ? sh[t - st] : 0;
        __syncthreads();
        sh[t] += add;
        __syncthreads();
    }
    // block-level exclusive offset (each block redundantly scans 64 sums)
    int boff = 0;
    for (int i = 0; i < b; i++) boff += __ldg(&g_blocksum[i]);

    int off = boff + sh[t] - s;              // exclusive prefix for this chunk
    int4 o;
    o.x = off;
    o.y = off + v.x;
    o.z = off + v.x + v.y;
    o.w = off + v.x + v.y + v.z;
    ((int4*)g_off)[base4] = o;
    ((int4*)g_cur)[base4] = o;
    ((int4*)g_deg)[base4] = make_int4(0, 0, 0, 0);   // reset for next call
    if (b == 63 && t == 255) g_off[NUM_GRID] = NUM_EDGES;
}

// ---------- CSR fill ----------
__global__ void k_fill(const int4* __restrict__ ei) {
    int i = blockIdx.x * blockDim.x + threadIdx.x;   // 2 edges per thread
    if (i < NUM_EDGES / 2) {
        int4 e = __ldg(&ei[i]);
        g_edges[atomicAdd(&g_cur[e.y], 1)] = e.x;
        g_edges[atomicAdd(&g_cur[e.w], 1)] = e.z;
    }
}

// ---------- gather: one warp per grid node, both batches ----------
__device__ __forceinline__ void facc(float4& a, const float4 v) {
    a.x += v.x; a.y += v.y; a.z += v.z; a.w += v.w;
}

__global__ void __launch_bounds__(256) k_gather(
    const float* __restrict__ feats, float* __restrict__ out)
{
    int warp = (blockIdx.x * blockDim.x + threadIdx.x) >> 5;
    int lane = threadIdx.x & 31;
    if (warp >= NUM_GRID) return;

    int beg = __ldg(&g_off[warp]);
    int end = __ldg(&g_off[warp + 1]);
    float inv = 1.0f / fmaxf((float)(end - beg), 1.0f);

    float4 a00 = make_float4(0.f,0.f,0.f,0.f), a01 = a00, a10 = a00, a11 = a00;

    int i = beg;
    // unroll by 2 edges for MLP: 8 float4 loads in flight
    for (; i + 2 <= end; i += 2) {
        int s0 = __ldg(&g_edges[i]);
        int s1 = __ldg(&g_edges[i + 1]);
        const float4* p00 = (const float4*)(feats + (long long)s0 * EMBED);
        const float4* p01 = (const float4*)(feats + ((long long)NUM_MESH + s0) * EMBED);
        const float4* p10 = (const float4*)(feats + (long long)s1 * EMBED);
        const float4* p11 = (const float4*)(feats + ((long long)NUM_MESH + s1) * EMBED);
        float4 v0 = __ldg(&p00[lane]);
        float4 v1 = __ldg(&p00[lane + 32]);
        float4 v2 = __ldg(&p01[lane]);
        float4 v3 = __ldg(&p01[lane + 32]);
        float4 v4 = __ldg(&p10[lane]);
        float4 v5 = __ldg(&p10[lane + 32]);
        float4 v6 = __ldg(&p11[lane]);
        float4 v7 = __ldg(&p11[lane + 32]);
        facc(a00, v0); facc(a01, v1); facc(a10, v2); facc(a11, v3);
        facc(a00, v4); facc(a01, v5); facc(a10, v6); facc(a11, v7);
    }
    if (i < end) {
        int s0 = __ldg(&g_edges[i]);
        const float4* p00 = (const float4*)(feats + (long long)s0 * EMBED);
        const float4* p01 = (const float4*)(feats + ((long long)NUM_MESH + s0) * EMBED);
        facc(a00, __ldg(&p00[lane]));
        facc(a01, __ldg(&p00[lane + 32]));
        facc(a10, __ldg(&p01[lane]));
        facc(a11, __ldg(&p01[lane + 32]));
    }

    a00.x *= inv; a00.y *= inv; a00.z *= inv; a00.w *= inv;
    a01.x *= inv; a01.y *= inv; a01.z *= inv; a01.w *= inv;
    a10.x *= inv; a10.y *= inv; a10.z *= inv; a10.w *= inv;
    a11.x *= inv; a11.y *= inv; a11.z *= inv; a11.w *= inv;

    // streaming (evict-first) stores: keep the feature table L2-resident
    float4* o0 = (float4*)(out + (long long)warp * EMBED);
    float4* o1 = (float4*)(out + ((long long)NUM_GRID + warp) * EMBED);
    __stcs(&o0[lane],      a00);
    __stcs(&o0[lane + 32], a01);
    __stcs(&o1[lane],      a10);
    __stcs(&o1[lane + 32], a11);
}

extern "C" void kernel_launch(void* const* d_in, const int* in_sizes, int n_in,
                              void* d_out, int out_size)
{
    const float* feats;
    const void* ei;
    if (in_sizes[0] == BATCH * NUM_MESH * EMBED) {
        feats = (const float*)d_in[0];
        ei    = d_in[1];
    } else {
        feats = (const float*)d_in[1];
        ei    = d_in[0];
    }
    float* out = (float*)d_out;

    k_deg <<<NUM_EDGES / 2 / 256, 256>>>((const int4*)ei);
    k_scan1<<<64, 256>>>();
    k_scan3<<<64, 256>>>();
    k_fill<<<NUM_EDGES / 2 / 256, 256>>>((const int4*)ei);
    // 65536 warps, 8 warps/block -> 8192 blocks
    k_gather<<<NUM_GRID / 8, 256>>>(feats, out);
}